// round 5
// baseline (speedup 1.0000x reference)
#include <cuda_runtime.h>
#include <cstdint>

// ---------------------------------------------------------------------------
// BatchTopK via exact threshold selection on float bit patterns.
//   k_zero:     reset hists / flags / tickets.
//   k_main:     read x (streaming), write out=0, detect >= 3.0 via max-tree +
//               divergent branch (warp skips ~71% of 8-float groups), compact
//               candidates (bits,idx) into per-warp slabs. No histogram here.
//   k_histscan: histogram candidates into 16384 bins (grid), last block does
//               suffix-scan -> threshold bin B*, c_above, k_total; sets
//               need_full if insufficient mass or slab overflow.
//   k_fallback: guarded single-block exact path (never runs on normal data).
//   k_sel:      scatter slab winners (bin > B*), boundary bin -> buffer; last
//               block refines exact threshold bits and resolves value ties by
//               smallest index (lax.top_k stable tie-break).
// ---------------------------------------------------------------------------

#define T_DET      3.0f
#define NBINS      16384
#define SLAB       32
#define NUM_WARPS  65536
#define BND_CAP    (2u << 20)        // == NUM_WARPS*SLAB worst case
#define TIE_CAP    4096
#define HS_GRID    64
#define SEL_GRID   128

__device__ unsigned g_hist[NBINS];
__device__ unsigned g_hist2[NBINS];     // fallback hist
__device__ int      g_B_star;
__device__ unsigned g_c_above;
__device__ unsigned g_k_total;
__device__ int      g_need_full;
__device__ int      g_overflow;
__device__ unsigned g_nb;
__device__ unsigned g_ticket1;
__device__ unsigned g_ticket2;
__device__ unsigned g_warp_cnt[NUM_WARPS];
__device__ uint2    g_cand[(size_t)NUM_WARPS * SLAB];
__device__ unsigned g_bnd_bits[BND_CAP];
__device__ unsigned g_bnd_idx[BND_CAP];

__global__ void k_zero() {
    int i = blockIdx.x * blockDim.x + threadIdx.x;
    int stride = gridDim.x * blockDim.x;
    for (int b = i; b < NBINS; b += stride) { g_hist[b] = 0u; g_hist2[b] = 0u; }
    if (i == 0) {
        g_need_full = 0; g_overflow = 0; g_nb = 0u;
        g_ticket1 = 0u; g_ticket2 = 0u;
        g_B_star = 0x7fffffff; g_c_above = 0u; g_k_total = 0u;
    }
}

__device__ __forceinline__ void handle4(float4 a, int i4, unsigned* wctr, uint2* slab) {
    float vals[4] = {a.x, a.y, a.z, a.w};
#pragma unroll
    for (int j = 0; j < 4; j++) {
        if (vals[j] >= T_DET) {
            unsigned pos = atomicAdd(wctr, 1u);
            if (pos < SLAB) slab[pos] = make_uint2(__float_as_uint(vals[j]),
                                                   (unsigned)(4 * i4 + j));
            else            g_overflow = 1;
        }
    }
}

// Fused streaming pass: zero output + candidate compaction.
__global__ void __launch_bounds__(1024, 1)
k_main(const float4* __restrict__ x4, float4* __restrict__ o4, int n4) {
    __shared__ unsigned wcnt[32];
    if (threadIdx.x < 32) wcnt[threadIdx.x] = 0u;
    __syncthreads();

    const int lane   = threadIdx.x & 31;
    const int wlocal = threadIdx.x >> 5;
    const int W      = blockIdx.x * 32 + wlocal;
    const int base   = W * 256;                   // 256 float4 per warp
    uint2*    slab   = g_cand + (size_t)W * SLAB;
    unsigned* wctr   = &wcnt[wlocal];
    const float4 z4  = make_float4(0.f, 0.f, 0.f, 0.f);

    if (base + 256 <= n4 && W < NUM_WARPS) {
        float4 v[8];
#pragma unroll
        for (int it = 0; it < 8; it++) v[it] = __ldcs(&x4[base + it * 32 + lane]);
#pragma unroll
        for (int it = 0; it < 8; it++) __stcs(&o4[base + it * 32 + lane], z4);
#pragma unroll
        for (int p = 0; p < 4; p++) {
            float4 a = v[2 * p], b = v[2 * p + 1];
            float m = fmaxf(fmaxf(fmaxf(a.x, a.y), fmaxf(a.z, a.w)),
                            fmaxf(fmaxf(b.x, b.y), fmaxf(b.z, b.w)));
            if (m >= T_DET) {     // warp skips this entirely ~71% of the time
                handle4(a, base + (2 * p) * 32 + lane, wctr, slab);
                handle4(b, base + (2 * p + 1) * 32 + lane, wctr, slab);
            }
        }
    } else {
        for (int it = 0; it < 8; it++) {
            int i4 = base + it * 32 + lane;
            if (i4 < n4) {
                float4 a = x4[i4];
                o4[i4] = z4;
                if (W < NUM_WARPS) handle4(a, i4, wctr, slab);
                else {
                    float vals[4] = {a.x, a.y, a.z, a.w};
                    for (int j = 0; j < 4; j++)
                        if (vals[j] >= T_DET) g_overflow = 1;
                }
            }
        }
    }
    __syncwarp();
    if (lane == 0 && W < NUM_WARPS) g_warp_cnt[W] = min(wcnt[wlocal], (unsigned)SLAB);
}

// Histogram candidates (grid) + last-block suffix scan.
__global__ void __launch_bounds__(1024, 1)
k_histscan(const int* __restrict__ kptr, int n, int nwarps) {
    int lane = threadIdx.x & 31;
    int w  = (blockIdx.x * blockDim.x + threadIdx.x) >> 5;
    int nw = (gridDim.x * blockDim.x) >> 5;
    for (int s = w; s < nwarps; s += nw) {
        unsigned cnt = g_warp_cnt[s];
        const uint2* slab = g_cand + (size_t)s * SLAB;
        for (unsigned e = lane; e < cnt; e += 32)
            atomicAdd(&g_hist[slab[e].x >> 17], 1u);
    }

    __shared__ int s_last;
    __threadfence();
    if (threadIdx.x == 0)
        s_last = (atomicAdd(&g_ticket1, 1u) == (unsigned)gridDim.x - 1u);
    __syncthreads();
    if (!s_last) return;

    // ---- last block: suffix scan of g_hist (coherent reads via __ldcg) ----
    __shared__ unsigned s_arr[1024];
    __shared__ int s_found;
    __shared__ unsigned sK;
    int t = threadIdx.x;
    if (t == 0) {
        s_found = 0;
        unsigned batch = (unsigned)(n >> 16);   // d_sae = 65536
        g_k_total = (unsigned)(*kptr) * batch;
        sK = g_k_total;
    }
    __syncthreads();
    unsigned K = sK;
    const int C = NBINS / 1024;   // 16
    unsigned h[C];
    unsigned a = 0;
#pragma unroll
    for (int jj = 0; jj < C; jj++) { h[jj] = __ldcg(&g_hist[t * C + jj]); a += h[jj]; }
    s_arr[t] = a;
    __syncthreads();
    for (int off = 1; off < 1024; off <<= 1) {
        unsigned v = (t + off < 1024) ? s_arr[t + off] : 0u;
        __syncthreads();
        s_arr[t] += v;
        __syncthreads();
    }
    unsigned running = s_arr[t] - a;
#pragma unroll
    for (int jj = C - 1; jj >= 0; --jj) {
        if (running < K && running + h[jj] >= K) {
            g_B_star = t * C + jj;
            g_c_above = running;
            s_found = 1;
        }
        running += h[jj];
    }
    __syncthreads();
    if (t == 0 && (!s_found || g_overflow)) g_need_full = 1;
}

// Shared refine+tie logic (block-wide; reads via __ldcg / atomic for coherence).
__device__ void sel2_body(float* __restrict__ out) {
    __shared__ unsigned h1[512];
    __shared__ unsigned h2[256];
    __shared__ unsigned tie_idx[TIE_CAP];
    __shared__ unsigned s_tcnt;
    __shared__ int s_s1;
    __shared__ unsigned s_c1;
    __shared__ unsigned s_Tbits;
    __shared__ unsigned s_r;
    __shared__ int s_mode;

    int t = threadIdx.x;
    unsigned nb = min(atomicAdd(&g_nb, 0u), (unsigned)BND_CAP);
    int B = g_B_star;
    unsigned K = g_k_total, ca = g_c_above;

    if (t == 0) {
        if (nb == 0u || ca >= K) s_mode = 2;
        else s_mode = ((K - ca) >= nb) ? 1 : 0;
    }
    __syncthreads();
    if (s_mode == 2) return;
    if (s_mode == 1) {
        for (unsigned i = t; i < nb; i += blockDim.x)
            out[__ldcg(&g_bnd_idx[i])] = __uint_as_float(__ldcg(&g_bnd_bits[i]));
        return;
    }
    unsigned m = K - ca;

    for (int i = t; i < 512; i += blockDim.x) h1[i] = 0u;
    __syncthreads();
    for (unsigned i = t; i < nb; i += blockDim.x)
        atomicAdd(&h1[(__ldcg(&g_bnd_bits[i]) >> 8) & 0x1FFu], 1u);
    __syncthreads();
    if (t == 0) {
        unsigned running = 0; int s1 = 0; unsigned c1 = 0;
        for (int j = 511; j >= 0; --j) {
            unsigned h = h1[j];
            if (running < m && running + h >= m) { s1 = j; c1 = running; break; }
            running += h;
        }
        s_s1 = s1; s_c1 = c1;
    }
    __syncthreads();
    int s1 = s_s1; unsigned c1 = s_c1;

    for (int i = t; i < 256; i += blockDim.x) h2[i] = 0u;
    __syncthreads();
    for (unsigned i = t; i < nb; i += blockDim.x) {
        unsigned bits = __ldcg(&g_bnd_bits[i]);
        if (((bits >> 8) & 0x1FFu) == (unsigned)s1)
            atomicAdd(&h2[bits & 0xFFu], 1u);
    }
    __syncthreads();
    if (t == 0) {
        unsigned m2 = m - c1;
        unsigned running = 0; int b2 = 0; unsigned c2 = 0;
        for (int j = 255; j >= 0; --j) {
            unsigned h = h2[j];
            if (running < m2 && running + h >= m2) { b2 = j; c2 = running; break; }
            running += h;
        }
        s_Tbits = ((unsigned)B << 17) | ((unsigned)s1 << 8) | (unsigned)b2;
        s_r = m2 - c2;
        s_tcnt = 0u;
    }
    __syncthreads();
    unsigned Tb = s_Tbits, r = s_r;

    for (unsigned i = t; i < nb; i += blockDim.x) {
        unsigned bits = __ldcg(&g_bnd_bits[i]);
        if (bits > Tb) {
            out[__ldcg(&g_bnd_idx[i])] = __uint_as_float(bits);
        } else if (bits == Tb) {
            unsigned p = atomicAdd(&s_tcnt, 1u);
            if (p < TIE_CAP) tie_idx[p] = __ldcg(&g_bnd_idx[i]);
        }
    }
    __syncthreads();
    unsigned tcnt = min(s_tcnt, (unsigned)TIE_CAP);
    if (r >= tcnt) {
        for (unsigned i = t; i < tcnt; i += blockDim.x)
            out[tie_idx[i]] = __uint_as_float(Tb);
        return;
    }
    for (unsigned i = t; i < TIE_CAP; i += blockDim.x)
        if (i >= tcnt) tie_idx[i] = 0xFFFFFFFFu;
    __syncthreads();
    for (unsigned kk = 2; kk <= TIE_CAP; kk <<= 1) {
        for (unsigned j = kk >> 1; j > 0; j >>= 1) {
            for (unsigned i = t; i < TIE_CAP; i += blockDim.x) {
                unsigned ixj = i ^ j;
                if (ixj > i) {
                    unsigned va = tie_idx[i], vb = tie_idx[ixj];
                    bool asc = ((i & kk) == 0);
                    if ((va > vb) == asc) { tie_idx[i] = vb; tie_idx[ixj] = va; }
                }
            }
            __syncthreads();
        }
    }
    for (unsigned i = t; i < r; i += blockDim.x)
        out[tie_idx[i]] = __uint_as_float(Tb);
}

// Guarded exact fallback: one block does everything (never runs on normal data).
__global__ void __launch_bounds__(1024, 1)
k_fallback(const float4* __restrict__ x4, float* __restrict__ out, int n4) {
    if (!g_need_full) return;
    int t = threadIdx.x;
    unsigned K = g_k_total;
    if (K == 0u) return;   // out already zeroed

    // full-range histogram of positives
    for (int i = t; i < n4; i += 1024) {
        float4 v = x4[i];
        float vals[4] = {v.x, v.y, v.z, v.w};
#pragma unroll
        for (int j = 0; j < 4; j++)
            if (vals[j] > 0.0f)
                atomicAdd(&g_hist2[__float_as_uint(vals[j]) >> 17], 1u);
    }
    __syncthreads();

    // suffix scan
    __shared__ unsigned s_arr[1024];
    __shared__ int s_found;
    const int C = NBINS / 1024;
    unsigned h[C];
    unsigned a = 0;
    if (t == 0) s_found = 0;
    __syncthreads();
#pragma unroll
    for (int jj = 0; jj < C; jj++) { h[jj] = g_hist2[t * C + jj]; a += h[jj]; }
    s_arr[t] = a;
    __syncthreads();
    for (int off = 1; off < 1024; off <<= 1) {
        unsigned v = (t + off < 1024) ? s_arr[t + off] : 0u;
        __syncthreads();
        s_arr[t] += v;
        __syncthreads();
    }
    unsigned running = s_arr[t] - a;
#pragma unroll
    for (int jj = C - 1; jj >= 0; --jj) {
        if (running < K && running + h[jj] >= K) {
            g_B_star = t * C + jj;
            g_c_above = running;
            s_found = 1;
        }
        running += h[jj];
    }
    __syncthreads();
    if (t == 0 && !s_found) { g_B_star = -1; g_c_above = s_arr[0]; }
    __syncthreads();

    // output pass: write winners, collect boundary
    int B = g_B_star;
    for (int i = t; i < n4; i += 1024) {
        float4 v = x4[i];
        float vals[4] = {v.x, v.y, v.z, v.w};
#pragma unroll
        for (int j = 0; j < 4; j++) {
            float val = vals[j];
            if (val > 0.0f) {
                unsigned u = __float_as_uint(val);
                int bin = (int)(u >> 17);
                if (bin > B) {
                    out[4 * i + j] = val;
                } else if (bin == B) {
                    unsigned p = atomicAdd(&g_nb, 1u);
                    if (p < BND_CAP) { g_bnd_bits[p] = u; g_bnd_idx[p] = (unsigned)(4 * i + j); }
                }
            }
        }
    }
    __syncthreads();
    sel2_body(out);
}

// Scatter winners from slabs, boundary -> buffer; last block refines.
__global__ void __launch_bounds__(1024, 1)
k_sel(float* __restrict__ out, int nwarps) {
    if (g_need_full) return;
    const int B = g_B_star;
    int lane = threadIdx.x & 31;
    int w  = (blockIdx.x * blockDim.x + threadIdx.x) >> 5;
    int nw = (gridDim.x * blockDim.x) >> 5;
    for (int s = w; s < nwarps; s += nw) {
        unsigned cnt = g_warp_cnt[s];
        const uint2* slab = g_cand + (size_t)s * SLAB;
        for (unsigned e = lane; e < cnt; e += 32) {
            uint2 c = slab[e];
            int bin = (int)(c.x >> 17);
            if (bin > B) {
                out[c.y] = __uint_as_float(c.x);
            } else if (bin == B) {
                unsigned p = atomicAdd(&g_nb, 1u);
                if (p < BND_CAP) { g_bnd_bits[p] = c.x; g_bnd_idx[p] = c.y; }
            }
        }
    }
    __shared__ int s_last;
    __threadfence();
    if (threadIdx.x == 0)
        s_last = (atomicAdd(&g_ticket2, 1u) == (unsigned)gridDim.x - 1u);
    __syncthreads();
    if (!s_last) return;
    sel2_body(out);
}

extern "C" void kernel_launch(void* const* d_in, const int* in_sizes, int n_in,
                              void* d_out, int out_size) {
    const float* x    = (const float*)d_in[0];
    const int*   kptr = (const int*)d_in[1];
    float*       out  = (float*)d_out;
    int n  = in_sizes[0];
    int n4 = n >> 2;

    int main_blocks = (n4 + (256 * 32) - 1) / (256 * 32);   // 2048 for 64M
    int nwarps = main_blocks * 32;
    if (nwarps > NUM_WARPS) nwarps = NUM_WARPS;

    k_zero<<<16, 1024>>>();
    k_main<<<main_blocks, 1024>>>((const float4*)x, (float4*)out, n4);
    k_histscan<<<HS_GRID, 1024>>>(kptr, n, nwarps);
    k_fallback<<<1, 1024>>>((const float4*)x, out, n4);     // guarded no-op
    k_sel<<<SEL_GRID, 1024>>>(out, nwarps);
}

// round 6
// speedup vs baseline: 1.0236x; 1.0236x over previous
#include <cuda_runtime.h>
#include <cstdint>

// ---------------------------------------------------------------------------
// BatchTopK via exact threshold selection on float bit patterns.
//   k_main:     read x, write out=0, detect >= 3.0 (max-tree + branch),
//               compact candidates into per-warp slabs (raw counts stored;
//               overflow detected later). Also zeroes all scratch state.
//   k_histscan: histogram candidates into 16384 bins; last block (ticket)
//               suffix-scans -> threshold bin B*, c_above, k_total, need_full.
//   k_sel:      normal: scatter slab winners, boundary bin -> buffer, last
//               block refines exact threshold + ties (smallest-index, i.e.
//               lax.top_k stable tie-break). Fallback (guarded, block 0 only):
//               exact full-range selection — never runs on normal data.
// ---------------------------------------------------------------------------

#define T_DET      3.0f
#define NBINS      16384
#define SLAB       32
#define NUM_WARPS  65536
#define BND_CAP    (1u << 20)
#define TIE_CAP    4096
#define HS_GRID    64
#define SEL_GRID   128

__device__ unsigned g_hist[NBINS];
__device__ unsigned g_hist2[NBINS];
__device__ int      g_B_star;
__device__ unsigned g_c_above;
__device__ unsigned g_k_total;
__device__ int      g_need_full;
__device__ int      g_ovf;
__device__ unsigned g_nb;
__device__ unsigned g_ticket1;
__device__ unsigned g_ticket2;
__device__ unsigned g_warp_cnt[NUM_WARPS];
__device__ uint2    g_cand[(size_t)NUM_WARPS * SLAB];
__device__ unsigned g_bnd_bits[BND_CAP];
__device__ unsigned g_bnd_idx[BND_CAP];

__device__ __forceinline__ void handle4(float4 a, int i4, unsigned* wctr, uint2* slab) {
    float vals[4] = {a.x, a.y, a.z, a.w};
#pragma unroll
    for (int j = 0; j < 4; j++) {
        if (vals[j] >= T_DET) {
            unsigned pos = atomicAdd(wctr, 1u);
            if (pos < SLAB) slab[pos] = make_uint2(__float_as_uint(vals[j]),
                                                   (unsigned)(4 * i4 + j));
        }
    }
}

// Fused: zero scratch state, zero output, candidate compaction.
__global__ void __launch_bounds__(1024, 1)
k_main(const float4* __restrict__ x4, float4* __restrict__ o4, int n4, int ntiles) {
    // --- zero scratch (locations written only by LATER kernels; no race) ---
    int gid = blockIdx.x * 1024 + threadIdx.x;
    if (gid < NBINS)                        g_hist[gid] = 0u;
    else if (gid < 2 * NBINS)               g_hist2[gid - NBINS] = 0u;
    if (gid == 0) { g_nb = 0u; g_ticket1 = 0u; g_ticket2 = 0u; g_ovf = 0; }

    __shared__ unsigned wcnt[32];
    if (threadIdx.x < 32) wcnt[threadIdx.x] = 0u;
    __syncthreads();

    const int lane   = threadIdx.x & 31;
    const int wlocal = threadIdx.x >> 5;
    const int W      = blockIdx.x * 32 + wlocal;
    const int NW     = gridDim.x * 32;
    uint2*    slab   = g_cand + (size_t)W * SLAB;
    unsigned* wctr   = &wcnt[wlocal];
    const float4 z4  = make_float4(0.f, 0.f, 0.f, 0.f);

    for (int tile = W; tile < ntiles; tile += NW) {
        const int base = tile * 256;              // 256 float4 per tile
        if (base + 256 <= n4) {
            float4 v[8];
#pragma unroll
            for (int it = 0; it < 8; it++) v[it] = x4[base + it * 32 + lane];
#pragma unroll
            for (int it = 0; it < 8; it++) o4[base + it * 32 + lane] = z4;
#pragma unroll
            for (int p = 0; p < 4; p++) {
                float4 a = v[2 * p], b = v[2 * p + 1];
                float m = fmaxf(fmaxf(fmaxf(a.x, a.y), fmaxf(a.z, a.w)),
                                fmaxf(fmaxf(b.x, b.y), fmaxf(b.z, b.w)));
                if (m >= T_DET) {
                    handle4(a, base + (2 * p) * 32 + lane, wctr, slab);
                    handle4(b, base + (2 * p + 1) * 32 + lane, wctr, slab);
                }
            }
        } else {
            for (int it = 0; it < 8; it++) {
                int i4 = base + it * 32 + lane;
                if (i4 < n4) {
                    float4 a = x4[i4];
                    o4[i4] = z4;
                    handle4(a, i4, wctr, slab);
                }
            }
        }
    }
    __syncwarp();
    if (lane == 0) g_warp_cnt[W] = wcnt[wlocal];   // raw count (uncapped)
}

// Histogram candidates; last block suffix-scans to find the threshold bin.
__global__ void __launch_bounds__(1024, 1)
k_histscan(const int* __restrict__ kptr, int n, int nwarps) {
    int lane = threadIdx.x & 31;
    int w  = (blockIdx.x * blockDim.x + threadIdx.x) >> 5;
    int nw = (gridDim.x * blockDim.x) >> 5;
    for (int s = w; s < nwarps; s += nw) {
        unsigned raw = g_warp_cnt[s];
        if (raw > SLAB && lane == 0) g_ovf = 1;
        unsigned cnt = min(raw, (unsigned)SLAB);
        const uint2* slab = g_cand + (size_t)s * SLAB;
        for (unsigned e = lane; e < cnt; e += 32)
            atomicAdd(&g_hist[slab[e].x >> 17], 1u);
    }

    __shared__ int s_last;
    __threadfence();
    if (threadIdx.x == 0)
        s_last = (atomicAdd(&g_ticket1, 1u) == (unsigned)gridDim.x - 1u);
    __syncthreads();
    if (!s_last) return;

    __shared__ unsigned s_arr[1024];
    __shared__ int s_found;
    __shared__ unsigned sK;
    int t = threadIdx.x;
    if (t == 0) {
        s_found = 0;
        unsigned batch = (unsigned)(n >> 16);   // d_sae = 65536
        g_k_total = (unsigned)(*kptr) * batch;
        sK = g_k_total;
    }
    __syncthreads();
    unsigned K = sK;
    const int C = NBINS / 1024;
    unsigned h[C];
    unsigned a = 0;
#pragma unroll
    for (int jj = 0; jj < C; jj++) { h[jj] = __ldcg(&g_hist[t * C + jj]); a += h[jj]; }
    s_arr[t] = a;
    __syncthreads();
    for (int off = 1; off < 1024; off <<= 1) {
        unsigned v = (t + off < 1024) ? s_arr[t + off] : 0u;
        __syncthreads();
        s_arr[t] += v;
        __syncthreads();
    }
    unsigned running = s_arr[t] - a;
#pragma unroll
    for (int jj = C - 1; jj >= 0; --jj) {
        if (running < K && running + h[jj] >= K) {
            g_B_star = t * C + jj;
            g_c_above = running;
            s_found = 1;
        }
        running += h[jj];
    }
    __syncthreads();
    if (t == 0) g_need_full = (!s_found || __ldcg((const int*)&g_ovf)) ? 1 : 0;
}

// Block-wide refine+tie logic over the boundary buffer.
__device__ void sel2_body(float* __restrict__ out) {
    __shared__ unsigned h1[512];
    __shared__ unsigned h2[256];
    __shared__ unsigned tie_idx[TIE_CAP];
    __shared__ unsigned s_tcnt;
    __shared__ int s_s1;
    __shared__ unsigned s_c1;
    __shared__ unsigned s_Tbits;
    __shared__ unsigned s_r;
    __shared__ int s_mode;

    int t = threadIdx.x;
    unsigned nb = min(atomicAdd(&g_nb, 0u), (unsigned)BND_CAP);
    int B = g_B_star;
    unsigned K = g_k_total, ca = g_c_above;

    if (t == 0) {
        if (nb == 0u || ca >= K) s_mode = 2;
        else s_mode = ((K - ca) >= nb) ? 1 : 0;
    }
    __syncthreads();
    if (s_mode == 2) return;
    if (s_mode == 1) {
        for (unsigned i = t; i < nb; i += blockDim.x)
            out[__ldcg(&g_bnd_idx[i])] = __uint_as_float(__ldcg(&g_bnd_bits[i]));
        return;
    }
    unsigned m = K - ca;

    for (int i = t; i < 512; i += blockDim.x) h1[i] = 0u;
    __syncthreads();
    for (unsigned i = t; i < nb; i += blockDim.x)
        atomicAdd(&h1[(__ldcg(&g_bnd_bits[i]) >> 8) & 0x1FFu], 1u);
    __syncthreads();
    if (t == 0) {
        unsigned running = 0; int s1 = 0; unsigned c1 = 0;
        for (int j = 511; j >= 0; --j) {
            unsigned h = h1[j];
            if (running < m && running + h >= m) { s1 = j; c1 = running; break; }
            running += h;
        }
        s_s1 = s1; s_c1 = c1;
    }
    __syncthreads();
    int s1 = s_s1; unsigned c1 = s_c1;

    for (int i = t; i < 256; i += blockDim.x) h2[i] = 0u;
    __syncthreads();
    for (unsigned i = t; i < nb; i += blockDim.x) {
        unsigned bits = __ldcg(&g_bnd_bits[i]);
        if (((bits >> 8) & 0x1FFu) == (unsigned)s1)
            atomicAdd(&h2[bits & 0xFFu], 1u);
    }
    __syncthreads();
    if (t == 0) {
        unsigned m2 = m - c1;
        unsigned running = 0; int b2 = 0; unsigned c2 = 0;
        for (int j = 255; j >= 0; --j) {
            unsigned h = h2[j];
            if (running < m2 && running + h >= m2) { b2 = j; c2 = running; break; }
            running += h;
        }
        s_Tbits = ((unsigned)B << 17) | ((unsigned)s1 << 8) | (unsigned)b2;
        s_r = m2 - c2;
        s_tcnt = 0u;
    }
    __syncthreads();
    unsigned Tb = s_Tbits, r = s_r;

    for (unsigned i = t; i < nb; i += blockDim.x) {
        unsigned bits = __ldcg(&g_bnd_bits[i]);
        if (bits > Tb) {
            out[__ldcg(&g_bnd_idx[i])] = __uint_as_float(bits);
        } else if (bits == Tb) {
            unsigned p = atomicAdd(&s_tcnt, 1u);
            if (p < TIE_CAP) tie_idx[p] = __ldcg(&g_bnd_idx[i]);
        }
    }
    __syncthreads();
    unsigned tcnt = min(s_tcnt, (unsigned)TIE_CAP);
    if (r >= tcnt) {
        for (unsigned i = t; i < tcnt; i += blockDim.x)
            out[tie_idx[i]] = __uint_as_float(Tb);
        return;
    }
    for (unsigned i = t; i < TIE_CAP; i += blockDim.x)
        if (i >= tcnt) tie_idx[i] = 0xFFFFFFFFu;
    __syncthreads();
    for (unsigned kk = 2; kk <= TIE_CAP; kk <<= 1) {
        for (unsigned j = kk >> 1; j > 0; j >>= 1) {
            for (unsigned i = t; i < TIE_CAP; i += blockDim.x) {
                unsigned ixj = i ^ j;
                if (ixj > i) {
                    unsigned va = tie_idx[i], vb = tie_idx[ixj];
                    bool asc = ((i & kk) == 0);
                    if ((va > vb) == asc) { tie_idx[i] = vb; tie_idx[ixj] = va; }
                }
            }
            __syncthreads();
        }
    }
    for (unsigned i = t; i < r; i += blockDim.x)
        out[tie_idx[i]] = __uint_as_float(Tb);
}

// Normal: scatter winners + refine. Fallback (guarded, block 0): exact path.
__global__ void __launch_bounds__(1024, 1)
k_sel(const float4* __restrict__ x4, float* __restrict__ out, int n4, int nwarps) {
    if (g_need_full) {
        if (blockIdx.x != 0) return;
        int t = threadIdx.x;
        unsigned K = g_k_total;
        if (K == 0u) return;   // out already zeroed

        for (int i = t; i < n4; i += 1024) {
            float4 v = x4[i];
            float vals[4] = {v.x, v.y, v.z, v.w};
#pragma unroll
            for (int j = 0; j < 4; j++)
                if (vals[j] > 0.0f)
                    atomicAdd(&g_hist2[__float_as_uint(vals[j]) >> 17], 1u);
        }
        __syncthreads();

        __shared__ unsigned s_arr[1024];
        __shared__ int s_found;
        const int C = NBINS / 1024;
        unsigned h[C];
        unsigned a = 0;
        if (t == 0) s_found = 0;
        __syncthreads();
#pragma unroll
        for (int jj = 0; jj < C; jj++) { h[jj] = g_hist2[t * C + jj]; a += h[jj]; }
        s_arr[t] = a;
        __syncthreads();
        for (int off = 1; off < 1024; off <<= 1) {
            unsigned v = (t + off < 1024) ? s_arr[t + off] : 0u;
            __syncthreads();
            s_arr[t] += v;
            __syncthreads();
        }
        unsigned running = s_arr[t] - a;
#pragma unroll
        for (int jj = C - 1; jj >= 0; --jj) {
            if (running < K && running + h[jj] >= K) {
                g_B_star = t * C + jj;
                g_c_above = running;
                s_found = 1;
            }
            running += h[jj];
        }
        __syncthreads();
        if (t == 0 && !s_found) { g_B_star = -1; g_c_above = s_arr[0]; }
        __syncthreads();

        int B = g_B_star;
        for (int i = t; i < n4; i += 1024) {
            float4 v = x4[i];
            float vals[4] = {v.x, v.y, v.z, v.w};
#pragma unroll
            for (int j = 0; j < 4; j++) {
                float val = vals[j];
                if (val > 0.0f) {
                    unsigned u = __float_as_uint(val);
                    int bin = (int)(u >> 17);
                    if (bin > B) {
                        out[4 * i + j] = val;
                    } else if (bin == B) {
                        unsigned p = atomicAdd(&g_nb, 1u);
                        if (p < BND_CAP) { g_bnd_bits[p] = u; g_bnd_idx[p] = (unsigned)(4 * i + j); }
                    }
                }
            }
        }
        __syncthreads();
        sel2_body(out);
        return;
    }

    const int B = g_B_star;
    int lane = threadIdx.x & 31;
    int w  = (blockIdx.x * blockDim.x + threadIdx.x) >> 5;
    int nw = (gridDim.x * blockDim.x) >> 5;
    for (int s = w; s < nwarps; s += nw) {
        unsigned cnt = min(g_warp_cnt[s], (unsigned)SLAB);
        const uint2* slab = g_cand + (size_t)s * SLAB;
        for (unsigned e = lane; e < cnt; e += 32) {
            uint2 c = slab[e];
            int bin = (int)(c.x >> 17);
            if (bin > B) {
                out[c.y] = __uint_as_float(c.x);
            } else if (bin == B) {
                unsigned p = atomicAdd(&g_nb, 1u);
                if (p < BND_CAP) { g_bnd_bits[p] = c.x; g_bnd_idx[p] = c.y; }
            }
        }
    }
    __shared__ int s_last;
    __threadfence();
    if (threadIdx.x == 0)
        s_last = (atomicAdd(&g_ticket2, 1u) == (unsigned)gridDim.x - 1u);
    __syncthreads();
    if (!s_last) return;
    sel2_body(out);
}

extern "C" void kernel_launch(void* const* d_in, const int* in_sizes, int n_in,
                              void* d_out, int out_size) {
    const float* x    = (const float*)d_in[0];
    const int*   kptr = (const int*)d_in[1];
    float*       out  = (float*)d_out;
    int n  = in_sizes[0];
    int n4 = n >> 2;

    int ntiles = (n4 + 255) / 256;
    int main_blocks = (ntiles + 31) / 32;                 // 2048 for 64M
    if (main_blocks > NUM_WARPS / 32) main_blocks = NUM_WARPS / 32;
    int nwarps = main_blocks * 32;

    k_main<<<main_blocks, 1024>>>((const float4*)x, (float4*)out, n4, ntiles);
    k_histscan<<<HS_GRID, 1024>>>(kptr, n, nwarps);
    k_sel<<<SEL_GRID, 1024>>>((const float4*)x, out, n4, nwarps);
}

// round 7
// speedup vs baseline: 1.1661x; 1.1392x over previous
#include <cuda_runtime.h>
#include <cstdint>

// ---------------------------------------------------------------------------
// BatchTopK via exact threshold selection on float bit patterns.
//   k_init: zero g_hist + g_ncand (state k_main itself consumes).
//   k_main: stream x, write out=0, detect >= 3.0 (max-tree + branch),
//           stage candidates in per-warp SMEM slabs; block-end hierarchical
//           reservation -> dense g_cand (coalesced) + 16384-bin hist adds.
//   k_scan: single block suffix-scans hist -> B*, c_above, k_total, need_full.
//   k_sel:  dense coalesced pass over candidates: scatter bin>B* winners,
//           boundary bin -> buffer; ticketed last block refines exact
//           threshold bits + ties by smallest index (lax.top_k tie-break).
//           Guarded exact fallback (block 0) for any distribution/overflow.
// ---------------------------------------------------------------------------

#define T_DET      3.0f
#define NBINS      16384
#define WSLAB      40
#define MAXBLKS    2048
#define CAND_CAP   (MAXBLKS * 32 * WSLAB)
#define BND_CAP    (1u << 20)
#define TIE_CAP    4096
#define SEL_GRID   128

__device__ unsigned g_hist[NBINS];
__device__ unsigned g_hist2[NBINS];
__device__ int      g_B_star;
__device__ unsigned g_c_above;
__device__ unsigned g_k_total;
__device__ int      g_need_full;
__device__ int      g_ovf;
__device__ unsigned g_nb;
__device__ unsigned g_ncand;
__device__ unsigned g_ticket2;
__device__ uint2    g_cand[CAND_CAP];
__device__ unsigned g_bnd_bits[BND_CAP];
__device__ unsigned g_bnd_idx[BND_CAP];

__global__ void k_init() {
    int i = blockIdx.x * blockDim.x + threadIdx.x;
    int stride = gridDim.x * blockDim.x;
    for (int b = i; b < NBINS; b += stride) g_hist[b] = 0u;
    if (i == 0) g_ncand = 0u;
}

__device__ __forceinline__ void handle4(float4 a, int i4, unsigned* wctr, uint2* slab) {
    float vals[4] = {a.x, a.y, a.z, a.w};
#pragma unroll
    for (int j = 0; j < 4; j++) {
        if (vals[j] >= T_DET) {
            unsigned pos = atomicAdd(wctr, 1u);
            if (pos < WSLAB) slab[pos] = make_uint2(__float_as_uint(vals[j]),
                                                    (unsigned)(4 * i4 + j));
        }
    }
}

// Streaming pass: zero out, compact candidates (smem), dense dump + hist.
__global__ void __launch_bounds__(1024, 1)
k_main(const float4* __restrict__ x4, float4* __restrict__ o4, int n4, int ntiles) {
    // zero scratch used only by LATER kernels (no race)
    int gid = blockIdx.x * 1024 + threadIdx.x;
    if (gid < NBINS) g_hist2[gid] = 0u;
    if (gid == NBINS) { g_nb = 0u; g_ticket2 = 0u; g_ovf = 0; }

    __shared__ uint2    sslab[32 * WSLAB];
    __shared__ unsigned wcnt[32];
    __shared__ unsigned woff[32];
    __shared__ unsigned s_base;
    if (threadIdx.x < 32) wcnt[threadIdx.x] = 0u;
    __syncthreads();

    const int lane   = threadIdx.x & 31;
    const int wlocal = threadIdx.x >> 5;
    const int W      = blockIdx.x * 32 + wlocal;
    const int NW     = gridDim.x * 32;
    uint2*    slab   = sslab + wlocal * WSLAB;
    unsigned* wctr   = &wcnt[wlocal];
    const float4 z4  = make_float4(0.f, 0.f, 0.f, 0.f);

    for (int tile = W; tile < ntiles; tile += NW) {
        const int base = tile * 256;              // 256 float4 per tile
        if (base + 256 <= n4) {
            float4 v[8];
#pragma unroll
            for (int it = 0; it < 8; it++) v[it] = x4[base + it * 32 + lane];
#pragma unroll
            for (int it = 0; it < 8; it++) o4[base + it * 32 + lane] = z4;
#pragma unroll
            for (int p = 0; p < 4; p++) {
                float4 a = v[2 * p], b = v[2 * p + 1];
                float m = fmaxf(fmaxf(fmaxf(a.x, a.y), fmaxf(a.z, a.w)),
                                fmaxf(fmaxf(b.x, b.y), fmaxf(b.z, b.w)));
                if (m >= T_DET) {
                    handle4(a, base + (2 * p) * 32 + lane, wctr, slab);
                    handle4(b, base + (2 * p + 1) * 32 + lane, wctr, slab);
                }
            }
        } else {
            for (int it = 0; it < 8; it++) {
                int i4 = base + it * 32 + lane;
                if (i4 < n4) {
                    float4 a = x4[i4];
                    o4[i4] = z4;
                    handle4(a, i4, wctr, slab);
                }
            }
        }
    }
    __syncthreads();

    // hierarchical reservation: warp 0 scans the 32 warp counts
    if (wlocal == 0) {
        unsigned raw = wcnt[lane];
        if (raw > WSLAB) g_ovf = 1;
        unsigned c = min(raw, (unsigned)WSLAB);
        unsigned x = c;
#pragma unroll
        for (int o = 1; o < 32; o <<= 1) {
            unsigned y = __shfl_up_sync(0xFFFFFFFFu, x, o);
            if (lane >= o) x += y;
        }
        woff[lane] = x - c;
        if (lane == 31) s_base = atomicAdd(&g_ncand, x);
    }
    __syncthreads();

    // coalesced dump + histogram
    unsigned cnt  = min(wcnt[wlocal], (unsigned)WSLAB);
    unsigned base = s_base + woff[wlocal];
    for (unsigned e = lane; e < cnt; e += 32) {
        uint2 c = slab[e];
        g_cand[base + e] = c;
        atomicAdd(&g_hist[c.x >> 17], 1u);
    }
}

// Single block: suffix scan -> threshold bin.
__global__ void __launch_bounds__(1024, 1)
k_scan(const int* __restrict__ kptr, int n) {
    __shared__ unsigned s_arr[1024];
    __shared__ int s_found;
    __shared__ unsigned sK;
    int t = threadIdx.x;
    if (t == 0) {
        s_found = 0;
        unsigned batch = (unsigned)(n >> 16);   // d_sae = 65536
        g_k_total = (unsigned)(*kptr) * batch;
        sK = g_k_total;
    }
    __syncthreads();
    unsigned K = sK;
    const int C = NBINS / 1024;
    unsigned h[C];
    unsigned a = 0;
#pragma unroll
    for (int jj = 0; jj < C; jj++) { h[jj] = __ldcg(&g_hist[t * C + jj]); a += h[jj]; }
    s_arr[t] = a;
    __syncthreads();
    for (int off = 1; off < 1024; off <<= 1) {
        unsigned v = (t + off < 1024) ? s_arr[t + off] : 0u;
        __syncthreads();
        s_arr[t] += v;
        __syncthreads();
    }
    unsigned running = s_arr[t] - a;
#pragma unroll
    for (int jj = C - 1; jj >= 0; --jj) {
        if (running < K && running + h[jj] >= K) {
            g_B_star = t * C + jj;
            g_c_above = running;
            s_found = 1;
        }
        running += h[jj];
    }
    __syncthreads();
    if (t == 0) g_need_full = (!s_found || __ldcg((const int*)&g_ovf)) ? 1 : 0;
}

// Block-wide refine+tie logic over the boundary buffer.
__device__ void sel2_body(float* __restrict__ out) {
    __shared__ unsigned h1[512];
    __shared__ unsigned h2[256];
    __shared__ unsigned tie_idx[TIE_CAP];
    __shared__ unsigned s_tcnt;
    __shared__ int s_s1;
    __shared__ unsigned s_c1;
    __shared__ unsigned s_Tbits;
    __shared__ unsigned s_r;
    __shared__ int s_mode;

    int t = threadIdx.x;
    unsigned nb = min(atomicAdd(&g_nb, 0u), (unsigned)BND_CAP);
    int B = g_B_star;
    unsigned K = g_k_total, ca = g_c_above;

    if (t == 0) {
        if (nb == 0u || ca >= K) s_mode = 2;
        else s_mode = ((K - ca) >= nb) ? 1 : 0;
    }
    __syncthreads();
    if (s_mode == 2) return;
    if (s_mode == 1) {
        for (unsigned i = t; i < nb; i += blockDim.x)
            out[__ldcg(&g_bnd_idx[i])] = __uint_as_float(__ldcg(&g_bnd_bits[i]));
        return;
    }
    unsigned m = K - ca;

    for (int i = t; i < 512; i += blockDim.x) h1[i] = 0u;
    __syncthreads();
    for (unsigned i = t; i < nb; i += blockDim.x)
        atomicAdd(&h1[(__ldcg(&g_bnd_bits[i]) >> 8) & 0x1FFu], 1u);
    __syncthreads();
    if (t == 0) {
        unsigned running = 0; int s1 = 0; unsigned c1 = 0;
        for (int j = 511; j >= 0; --j) {
            unsigned h = h1[j];
            if (running < m && running + h >= m) { s1 = j; c1 = running; break; }
            running += h;
        }
        s_s1 = s1; s_c1 = c1;
    }
    __syncthreads();
    int s1 = s_s1; unsigned c1 = s_c1;

    for (int i = t; i < 256; i += blockDim.x) h2[i] = 0u;
    __syncthreads();
    for (unsigned i = t; i < nb; i += blockDim.x) {
        unsigned bits = __ldcg(&g_bnd_bits[i]);
        if (((bits >> 8) & 0x1FFu) == (unsigned)s1)
            atomicAdd(&h2[bits & 0xFFu], 1u);
    }
    __syncthreads();
    if (t == 0) {
        unsigned m2 = m - c1;
        unsigned running = 0; int b2 = 0; unsigned c2 = 0;
        for (int j = 255; j >= 0; --j) {
            unsigned h = h2[j];
            if (running < m2 && running + h >= m2) { b2 = j; c2 = running; break; }
            running += h;
        }
        s_Tbits = ((unsigned)B << 17) | ((unsigned)s1 << 8) | (unsigned)b2;
        s_r = m2 - c2;
        s_tcnt = 0u;
    }
    __syncthreads();
    unsigned Tb = s_Tbits, r = s_r;

    for (unsigned i = t; i < nb; i += blockDim.x) {
        unsigned bits = __ldcg(&g_bnd_bits[i]);
        if (bits > Tb) {
            out[__ldcg(&g_bnd_idx[i])] = __uint_as_float(bits);
        } else if (bits == Tb) {
            unsigned p = atomicAdd(&s_tcnt, 1u);
            if (p < TIE_CAP) tie_idx[p] = __ldcg(&g_bnd_idx[i]);
        }
    }
    __syncthreads();
    unsigned tcnt = min(s_tcnt, (unsigned)TIE_CAP);
    if (r >= tcnt) {
        for (unsigned i = t; i < tcnt; i += blockDim.x)
            out[tie_idx[i]] = __uint_as_float(Tb);
        return;
    }
    for (unsigned i = t; i < TIE_CAP; i += blockDim.x)
        if (i >= tcnt) tie_idx[i] = 0xFFFFFFFFu;
    __syncthreads();
    for (unsigned kk = 2; kk <= TIE_CAP; kk <<= 1) {
        for (unsigned j = kk >> 1; j > 0; j >>= 1) {
            for (unsigned i = t; i < TIE_CAP; i += blockDim.x) {
                unsigned ixj = i ^ j;
                if (ixj > i) {
                    unsigned va = tie_idx[i], vb = tie_idx[ixj];
                    bool asc = ((i & kk) == 0);
                    if ((va > vb) == asc) { tie_idx[i] = vb; tie_idx[ixj] = va; }
                }
            }
            __syncthreads();
        }
    }
    for (unsigned i = t; i < r; i += blockDim.x)
        out[tie_idx[i]] = __uint_as_float(Tb);
}

// Dense selection pass + last-block refine. Fallback (guarded, block 0).
__global__ void __launch_bounds__(1024, 1)
k_sel(const float4* __restrict__ x4, float* __restrict__ out, int n4) {
    if (g_need_full) {
        if (blockIdx.x != 0) return;
        int t = threadIdx.x;
        unsigned K = g_k_total;
        if (K == 0u) return;

        for (int i = t; i < n4; i += 1024) {
            float4 v = x4[i];
            float vals[4] = {v.x, v.y, v.z, v.w};
#pragma unroll
            for (int j = 0; j < 4; j++)
                if (vals[j] > 0.0f)
                    atomicAdd(&g_hist2[__float_as_uint(vals[j]) >> 17], 1u);
        }
        __syncthreads();

        __shared__ unsigned s_arr[1024];
        __shared__ int s_found;
        const int C = NBINS / 1024;
        unsigned h[C];
        unsigned a = 0;
        if (t == 0) s_found = 0;
        __syncthreads();
#pragma unroll
        for (int jj = 0; jj < C; jj++) { h[jj] = g_hist2[t * C + jj]; a += h[jj]; }
        s_arr[t] = a;
        __syncthreads();
        for (int off = 1; off < 1024; off <<= 1) {
            unsigned v = (t + off < 1024) ? s_arr[t + off] : 0u;
            __syncthreads();
            s_arr[t] += v;
            __syncthreads();
        }
        unsigned running = s_arr[t] - a;
#pragma unroll
        for (int jj = C - 1; jj >= 0; --jj) {
            if (running < K && running + h[jj] >= K) {
                g_B_star = t * C + jj;
                g_c_above = running;
                s_found = 1;
            }
            running += h[jj];
        }
        __syncthreads();
        if (t == 0 && !s_found) { g_B_star = -1; g_c_above = s_arr[0]; }
        __syncthreads();

        int B = g_B_star;
        for (int i = t; i < n4; i += 1024) {
            float4 v = x4[i];
            float vals[4] = {v.x, v.y, v.z, v.w};
#pragma unroll
            for (int j = 0; j < 4; j++) {
                float val = vals[j];
                if (val > 0.0f) {
                    unsigned u = __float_as_uint(val);
                    int bin = (int)(u >> 17);
                    if (bin > B) {
                        out[4 * i + j] = val;
                    } else if (bin == B) {
                        unsigned p = atomicAdd(&g_nb, 1u);
                        if (p < BND_CAP) { g_bnd_bits[p] = u; g_bnd_idx[p] = (unsigned)(4 * i + j); }
                    }
                }
            }
        }
        __syncthreads();
        sel2_body(out);
        return;
    }

    // normal path: one coalesced pass over dense candidates
    const int B = g_B_star;
    unsigned nc = min(__ldcg(&g_ncand), (unsigned)CAND_CAP);
    unsigned stride = gridDim.x * blockDim.x;
    for (unsigned i = blockIdx.x * blockDim.x + threadIdx.x; i < nc; i += stride) {
        uint2 c = g_cand[i];
        int bin = (int)(c.x >> 17);
        if (bin > B) {
            out[c.y] = __uint_as_float(c.x);
        } else if (bin == B) {
            unsigned p = atomicAdd(&g_nb, 1u);
            if (p < BND_CAP) { g_bnd_bits[p] = c.x; g_bnd_idx[p] = c.y; }
        }
    }
    __shared__ int s_last;
    __threadfence();
    if (threadIdx.x == 0)
        s_last = (atomicAdd(&g_ticket2, 1u) == (unsigned)gridDim.x - 1u);
    __syncthreads();
    if (!s_last) return;
    sel2_body(out);
}

extern "C" void kernel_launch(void* const* d_in, const int* in_sizes, int n_in,
                              void* d_out, int out_size) {
    const float* x    = (const float*)d_in[0];
    const int*   kptr = (const int*)d_in[1];
    float*       out  = (float*)d_out;
    int n  = in_sizes[0];
    int n4 = n >> 2;

    int ntiles = (n4 + 255) / 256;
    int main_blocks = (ntiles + 31) / 32;
    if (main_blocks > MAXBLKS) main_blocks = MAXBLKS;

    k_init<<<16, 1024>>>();
    k_main<<<main_blocks, 1024>>>((const float4*)x, (float4*)out, n4, ntiles);
    k_scan<<<1, 1024>>>(kptr, n);
    k_sel<<<SEL_GRID, 1024>>>((const float4*)x, out, n4);
}

// round 8
// speedup vs baseline: 1.1717x; 1.0048x over previous
#include <cuda_runtime.h>
#include <cstdint>

// ---------------------------------------------------------------------------
// BatchTopK via exact threshold selection on float bit patterns.
//   k_init:    zero g_hist + g_ncand.
//   k_main:    stream x, write out=0, detect >= 3.0 (max-tree + branch),
//              stage candidates in per-warp SMEM slabs; block-end reservation
//              -> dense g_cand (coalesced) + 16384-bin hist adds.
//   k_scan:    single block suffix-scans hist -> B*, c_above, k_total,
//              need_full.
//   k_scatter: dense coalesced pass: scatter bin>B* winners, boundary -> buf.
//   k_refine:  single block refines exact threshold bits + ties by smallest
//              index (lax.top_k tie-break); guarded exact fallback.
// NO __threadfence / last-block tickets anywhere (measured ~65us fixed cost
// per ticketed kernel on GB300); cross-kernel visibility via launch ordering.
// ---------------------------------------------------------------------------

#define T_DET      3.0f
#define NBINS      16384
#define WSLAB      40
#define MAXBLKS    2048
#define CAND_CAP   (MAXBLKS * 32 * WSLAB)
#define BND_CAP    (1u << 20)
#define TIE_CAP    4096
#define SCAT_GRID  128

__device__ unsigned g_hist[NBINS];
__device__ unsigned g_hist2[NBINS];
__device__ int      g_B_star;
__device__ unsigned g_c_above;
__device__ unsigned g_k_total;
__device__ int      g_need_full;
__device__ int      g_ovf;
__device__ unsigned g_nb;
__device__ unsigned g_ncand;
__device__ uint2    g_cand[CAND_CAP];
__device__ unsigned g_bnd_bits[BND_CAP];
__device__ unsigned g_bnd_idx[BND_CAP];

__global__ void k_init() {
    int i = blockIdx.x * blockDim.x + threadIdx.x;
    int stride = gridDim.x * blockDim.x;
    for (int b = i; b < NBINS; b += stride) g_hist[b] = 0u;
    if (i == 0) g_ncand = 0u;
}

__device__ __forceinline__ void handle4(float4 a, int i4, unsigned* wctr, uint2* slab) {
    float vals[4] = {a.x, a.y, a.z, a.w};
#pragma unroll
    for (int j = 0; j < 4; j++) {
        if (vals[j] >= T_DET) {
            unsigned pos = atomicAdd(wctr, 1u);
            if (pos < WSLAB) slab[pos] = make_uint2(__float_as_uint(vals[j]),
                                                    (unsigned)(4 * i4 + j));
        }
    }
}

// Streaming pass: zero out, compact candidates (smem), dense dump + hist.
__global__ void __launch_bounds__(1024, 1)
k_main(const float4* __restrict__ x4, float4* __restrict__ o4, int n4, int ntiles) {
    // zero scratch used only by LATER kernels (no race)
    int gid = blockIdx.x * 1024 + threadIdx.x;
    if (gid < NBINS) g_hist2[gid] = 0u;
    if (gid == NBINS) { g_nb = 0u; g_ovf = 0; }

    __shared__ uint2    sslab[32 * WSLAB];
    __shared__ unsigned wcnt[32];
    __shared__ unsigned woff[32];
    __shared__ unsigned s_base;
    if (threadIdx.x < 32) wcnt[threadIdx.x] = 0u;
    __syncthreads();

    const int lane   = threadIdx.x & 31;
    const int wlocal = threadIdx.x >> 5;
    const int W      = blockIdx.x * 32 + wlocal;
    const int NW     = gridDim.x * 32;
    uint2*    slab   = sslab + wlocal * WSLAB;
    unsigned* wctr   = &wcnt[wlocal];
    const float4 z4  = make_float4(0.f, 0.f, 0.f, 0.f);

    for (int tile = W; tile < ntiles; tile += NW) {
        const int base = tile * 256;              // 256 float4 per tile
        if (base + 256 <= n4) {
            float4 v[8];
#pragma unroll
            for (int it = 0; it < 8; it++) v[it] = x4[base + it * 32 + lane];
#pragma unroll
            for (int it = 0; it < 8; it++) o4[base + it * 32 + lane] = z4;
#pragma unroll
            for (int p = 0; p < 4; p++) {
                float4 a = v[2 * p], b = v[2 * p + 1];
                float m = fmaxf(fmaxf(fmaxf(a.x, a.y), fmaxf(a.z, a.w)),
                                fmaxf(fmaxf(b.x, b.y), fmaxf(b.z, b.w)));
                if (m >= T_DET) {
                    handle4(a, base + (2 * p) * 32 + lane, wctr, slab);
                    handle4(b, base + (2 * p + 1) * 32 + lane, wctr, slab);
                }
            }
        } else {
            for (int it = 0; it < 8; it++) {
                int i4 = base + it * 32 + lane;
                if (i4 < n4) {
                    float4 a = x4[i4];
                    o4[i4] = z4;
                    handle4(a, i4, wctr, slab);
                }
            }
        }
    }
    __syncthreads();

    // hierarchical reservation: warp 0 scans the 32 warp counts
    if (wlocal == 0) {
        unsigned raw = wcnt[lane];
        if (raw > WSLAB) g_ovf = 1;
        unsigned c = min(raw, (unsigned)WSLAB);
        unsigned x = c;
#pragma unroll
        for (int o = 1; o < 32; o <<= 1) {
            unsigned y = __shfl_up_sync(0xFFFFFFFFu, x, o);
            if (lane >= o) x += y;
        }
        woff[lane] = x - c;
        if (lane == 31) s_base = atomicAdd(&g_ncand, x);
    }
    __syncthreads();

    // coalesced dump + histogram
    unsigned cnt  = min(wcnt[wlocal], (unsigned)WSLAB);
    unsigned base = s_base + woff[wlocal];
    for (unsigned e = lane; e < cnt; e += 32) {
        uint2 c = slab[e];
        g_cand[base + e] = c;
        atomicAdd(&g_hist[c.x >> 17], 1u);
    }
}

// Single block: suffix scan -> threshold bin.
__global__ void __launch_bounds__(1024, 1)
k_scan(const int* __restrict__ kptr, int n) {
    __shared__ unsigned s_arr[1024];
    __shared__ int s_found;
    __shared__ unsigned sK;
    int t = threadIdx.x;
    if (t == 0) {
        s_found = 0;
        unsigned batch = (unsigned)(n >> 16);   // d_sae = 65536
        g_k_total = (unsigned)(*kptr) * batch;
        sK = g_k_total;
    }
    __syncthreads();
    unsigned K = sK;
    const int C = NBINS / 1024;
    unsigned h[C];
    unsigned a = 0;
#pragma unroll
    for (int jj = 0; jj < C; jj++) { h[jj] = __ldcg(&g_hist[t * C + jj]); a += h[jj]; }
    s_arr[t] = a;
    __syncthreads();
    for (int off = 1; off < 1024; off <<= 1) {
        unsigned v = (t + off < 1024) ? s_arr[t + off] : 0u;
        __syncthreads();
        s_arr[t] += v;
        __syncthreads();
    }
    unsigned running = s_arr[t] - a;
#pragma unroll
    for (int jj = C - 1; jj >= 0; --jj) {
        if (running < K && running + h[jj] >= K) {
            g_B_star = t * C + jj;
            g_c_above = running;
            s_found = 1;
        }
        running += h[jj];
    }
    __syncthreads();
    if (t == 0) g_need_full = (!s_found || __ldcg((const int*)&g_ovf)) ? 1 : 0;
}

// Dense coalesced selection pass (no fence, no ticket).
__global__ void __launch_bounds__(1024, 1)
k_scatter(float* __restrict__ out) {
    if (g_need_full) return;
    const int B = g_B_star;
    unsigned nc = min(__ldcg(&g_ncand), (unsigned)CAND_CAP);
    unsigned stride = gridDim.x * blockDim.x;
    for (unsigned i = blockIdx.x * blockDim.x + threadIdx.x; i < nc; i += stride) {
        uint2 c = g_cand[i];
        int bin = (int)(c.x >> 17);
        if (bin > B) {
            out[c.y] = __uint_as_float(c.x);
        } else if (bin == B) {
            unsigned p = atomicAdd(&g_nb, 1u);
            if (p < BND_CAP) { g_bnd_bits[p] = c.x; g_bnd_idx[p] = c.y; }
        }
    }
}

// Block-wide refine+tie logic over the boundary buffer.
__device__ void sel2_body(float* __restrict__ out) {
    __shared__ unsigned h1[512];
    __shared__ unsigned h2[256];
    __shared__ unsigned tie_idx[TIE_CAP];
    __shared__ unsigned s_tcnt;
    __shared__ int s_s1;
    __shared__ unsigned s_c1;
    __shared__ unsigned s_Tbits;
    __shared__ unsigned s_r;
    __shared__ int s_mode;

    int t = threadIdx.x;
    unsigned nb = min(g_nb, (unsigned)BND_CAP);
    int B = g_B_star;
    unsigned K = g_k_total, ca = g_c_above;

    if (t == 0) {
        if (nb == 0u || ca >= K) s_mode = 2;
        else s_mode = ((K - ca) >= nb) ? 1 : 0;
    }
    __syncthreads();
    if (s_mode == 2) return;
    if (s_mode == 1) {
        for (unsigned i = t; i < nb; i += blockDim.x)
            out[g_bnd_idx[i]] = __uint_as_float(g_bnd_bits[i]);
        return;
    }
    unsigned m = K - ca;

    for (int i = t; i < 512; i += blockDim.x) h1[i] = 0u;
    __syncthreads();
    for (unsigned i = t; i < nb; i += blockDim.x)
        atomicAdd(&h1[(g_bnd_bits[i] >> 8) & 0x1FFu], 1u);
    __syncthreads();
    if (t == 0) {
        unsigned running = 0; int s1 = 0; unsigned c1 = 0;
        for (int j = 511; j >= 0; --j) {
            unsigned h = h1[j];
            if (running < m && running + h >= m) { s1 = j; c1 = running; break; }
            running += h;
        }
        s_s1 = s1; s_c1 = c1;
    }
    __syncthreads();
    int s1 = s_s1; unsigned c1 = s_c1;

    for (int i = t; i < 256; i += blockDim.x) h2[i] = 0u;
    __syncthreads();
    for (unsigned i = t; i < nb; i += blockDim.x) {
        unsigned bits = g_bnd_bits[i];
        if (((bits >> 8) & 0x1FFu) == (unsigned)s1)
            atomicAdd(&h2[bits & 0xFFu], 1u);
    }
    __syncthreads();
    if (t == 0) {
        unsigned m2 = m - c1;
        unsigned running = 0; int b2 = 0; unsigned c2 = 0;
        for (int j = 255; j >= 0; --j) {
            unsigned h = h2[j];
            if (running < m2 && running + h >= m2) { b2 = j; c2 = running; break; }
            running += h;
        }
        s_Tbits = ((unsigned)B << 17) | ((unsigned)s1 << 8) | (unsigned)b2;
        s_r = m2 - c2;
        s_tcnt = 0u;
    }
    __syncthreads();
    unsigned Tb = s_Tbits, r = s_r;

    for (unsigned i = t; i < nb; i += blockDim.x) {
        unsigned bits = g_bnd_bits[i];
        if (bits > Tb) {
            out[g_bnd_idx[i]] = __uint_as_float(bits);
        } else if (bits == Tb) {
            unsigned p = atomicAdd(&s_tcnt, 1u);
            if (p < TIE_CAP) tie_idx[p] = g_bnd_idx[i];
        }
    }
    __syncthreads();
    unsigned tcnt = min(s_tcnt, (unsigned)TIE_CAP);
    if (r >= tcnt) {
        for (unsigned i = t; i < tcnt; i += blockDim.x)
            out[tie_idx[i]] = __uint_as_float(Tb);
        return;
    }
    for (unsigned i = t; i < TIE_CAP; i += blockDim.x)
        if (i >= tcnt) tie_idx[i] = 0xFFFFFFFFu;
    __syncthreads();
    for (unsigned kk = 2; kk <= TIE_CAP; kk <<= 1) {
        for (unsigned j = kk >> 1; j > 0; j >>= 1) {
            for (unsigned i = t; i < TIE_CAP; i += blockDim.x) {
                unsigned ixj = i ^ j;
                if (ixj > i) {
                    unsigned va = tie_idx[i], vb = tie_idx[ixj];
                    bool asc = ((i & kk) == 0);
                    if ((va > vb) == asc) { tie_idx[i] = vb; tie_idx[ixj] = va; }
                }
            }
            __syncthreads();
        }
    }
    for (unsigned i = t; i < r; i += blockDim.x)
        out[tie_idx[i]] = __uint_as_float(Tb);
}

// Single block: boundary refinement; guarded exact fallback.
__global__ void __launch_bounds__(1024, 1)
k_refine(const float4* __restrict__ x4, float* __restrict__ out, int n4) {
    if (g_need_full) {
        int t = threadIdx.x;
        unsigned K = g_k_total;
        if (K == 0u) return;   // out already zeroed

        for (int i = t; i < n4; i += 1024) {
            float4 v = x4[i];
            float vals[4] = {v.x, v.y, v.z, v.w};
#pragma unroll
            for (int j = 0; j < 4; j++)
                if (vals[j] > 0.0f)
                    atomicAdd(&g_hist2[__float_as_uint(vals[j]) >> 17], 1u);
        }
        __syncthreads();

        __shared__ unsigned s_arr[1024];
        __shared__ int s_found;
        const int C = NBINS / 1024;
        unsigned h[C];
        unsigned a = 0;
        if (t == 0) s_found = 0;
        __syncthreads();
#pragma unroll
        for (int jj = 0; jj < C; jj++) { h[jj] = g_hist2[t * C + jj]; a += h[jj]; }
        s_arr[t] = a;
        __syncthreads();
        for (int off = 1; off < 1024; off <<= 1) {
            unsigned v = (t + off < 1024) ? s_arr[t + off] : 0u;
            __syncthreads();
            s_arr[t] += v;
            __syncthreads();
        }
        unsigned running = s_arr[t] - a;
#pragma unroll
        for (int jj = C - 1; jj >= 0; --jj) {
            if (running < K && running + h[jj] >= K) {
                g_B_star = t * C + jj;
                g_c_above = running;
                s_found = 1;
            }
            running += h[jj];
        }
        __syncthreads();
        if (t == 0 && !s_found) { g_B_star = -1; g_c_above = s_arr[0]; }
        __syncthreads();

        int B = g_B_star;
        for (int i = t; i < n4; i += 1024) {
            float4 v = x4[i];
            float vals[4] = {v.x, v.y, v.z, v.w};
#pragma unroll
            for (int j = 0; j < 4; j++) {
                float val = vals[j];
                if (val > 0.0f) {
                    unsigned u = __float_as_uint(val);
                    int bin = (int)(u >> 17);
                    if (bin > B) {
                        out[4 * i + j] = val;
                    } else if (bin == B) {
                        unsigned p = atomicAdd(&g_nb, 1u);
                        if (p < BND_CAP) { g_bnd_bits[p] = u; g_bnd_idx[p] = (unsigned)(4 * i + j); }
                    }
                }
            }
        }
        __syncthreads();
        sel2_body(out);
        return;
    }
    sel2_body(out);
}

extern "C" void kernel_launch(void* const* d_in, const int* in_sizes, int n_in,
                              void* d_out, int out_size) {
    const float* x    = (const float*)d_in[0];
    const int*   kptr = (const int*)d_in[1];
    float*       out  = (float*)d_out;
    int n  = in_sizes[0];
    int n4 = n >> 2;

    int ntiles = (n4 + 255) / 256;
    int main_blocks = (ntiles + 31) / 32;
    if (main_blocks > MAXBLKS) main_blocks = MAXBLKS;

    k_init<<<16, 1024>>>();
    k_main<<<main_blocks, 1024>>>((const float4*)x, (float4*)out, n4, ntiles);
    k_scan<<<1, 1024>>>(kptr, n);
    k_scatter<<<SCAT_GRID, 1024>>>(out);
    k_refine<<<1, 1024>>>((const float4*)x, out, n4);
}